// round 1
// baseline (speedup 1.0000x reference)
#include <cuda_runtime.h>
#include <math.h>

// Problem constants
#define NB   8
#define NS   512
#define ND   1024
#define NH   16
#define NHD  64
#define S2   1024            // 2*NS, attention sequence length
#define BSq  (NB*NS)         // 4096 rows per branch
#define BT   (NB*S2)         // 8192 attention tokens
#define D3   3072
#define D4   4096

// ---------------------------------------------------------------------------
// Scratch (device globals; no runtime allocation allowed)
// ---------------------------------------------------------------------------
__device__ float g_xs  [BSq * ND];   // modulated state input
__device__ float g_xa  [BSq * ND];   // modulated action input
__device__ float g_qkvs[BSq * D3];   // qkv_s
__device__ float g_qkva[BSq * D3];   // qkv_a
__device__ float g_q   [BT * ND];    // roped, concatenated q
__device__ float g_k   [BT * ND];    // roped, concatenated k
__device__ float g_v   [BT * ND];    // concatenated v
__device__ float g_qh  [BT * ND];    // head-major q  (B,H,S2,HD)
__device__ float g_kh  [BT * ND];
__device__ float g_vh  [BT * ND];
__device__ float g_o   [BT * ND];    // attention output, token-major
__device__ float g_y   [BT * ND];    // after out-proj
__device__ float g_h1  [BSq * D4];   // MLP hidden (reused per branch)

// ---------------------------------------------------------------------------
// K0: modulation  x = (1 + scale)*z + shift   (scale/shift per batch from e)
// ---------------------------------------------------------------------------
__global__ void modulate_kernel(const float* __restrict__ sz,
                                const float* __restrict__ az,
                                const float* __restrict__ e)
{
    int idx = blockIdx.x * blockDim.x + threadIdx.x;
    if (idx >= BSq * ND) return;
    int b = idx >> 19;          // S*D = 2^19
    int k = idx & (ND - 1);
    const float* eb = e + b * 3 * ND;
    float sc = 1.0f + eb[ND + k];
    float sh = eb[k];
    g_xs[idx] = sc * sz[idx] + sh;
    g_xa[idx] = sc * az[idx] + sh;
}

// ---------------------------------------------------------------------------
// K2: RoPE over full D for q and k, copy for v; concat state(0..511) and
// action(512..1023) along the sequence. Position restarts at 0 for action.
// ---------------------------------------------------------------------------
__global__ void rope_kernel()
{
    int idx = blockIdx.x * blockDim.x + threadIdx.x;
    if (idx >= NB * S2 * (ND / 2)) return;
    int i = idx & 511;                 // pair index 0..511
    int t = (idx >> 9) & (S2 - 1);     // token 0..1023
    int b = idx >> 19;
    const float* src;
    int s;
    if (t < NS) { src = g_qkvs; s = t; }
    else        { src = g_qkva; s = t - NS; }
    const float* row = src + (b * NS + s) * D3;

    // inv = exp(-log(512) * (2i)/1024), theta = s * inv
    float inv = expf(-6.238324625039508f * (float)(2 * i) * (1.0f / 1024.0f));
    float th  = (float)s * inv;
    float sn, c;
    sincosf(th, &sn, &c);

    int dst = (b * S2 + t) * ND + 2 * i;
    // q
    {
        float xe = row[2 * i], xo = row[2 * i + 1];
        g_q[dst]     = xe * c - xo * sn;
        g_q[dst + 1] = xe * sn + xo * c;
    }
    // k
    {
        float xe = row[ND + 2 * i], xo = row[ND + 2 * i + 1];
        g_k[dst]     = xe * c - xo * sn;
        g_k[dst + 1] = xe * sn + xo * c;
    }
    // v (no rope)
    g_v[dst]     = row[2 * ND + 2 * i];
    g_v[dst + 1] = row[2 * ND + 2 * i + 1];
}

// ---------------------------------------------------------------------------
// Generic SGEMM:  C[M,N] = A[M,K] @ W[N,K]^T + bias[N]  with fused epilogues.
//   epi 0: plain store (row-major)
//   epi 1: store in head-major layout (B,H,S2,HD)
//   epi 2: gelu(tanh approx)
//   epi 3: out = Z + C * residual(e)    (MLP2 + gated residual)
//   a_split: logical row m maps to physical row (m/512)*1024 + a_half*512 + m%512
// 128x128 block tile, 8x8 per thread, BK=8, 256 threads.
// ---------------------------------------------------------------------------
#define BM 128
#define BN 128
#define BKT 8

__global__ void __launch_bounds__(256) sgemm_kernel(
    const float* __restrict__ A, const float* __restrict__ W,
    const float* __restrict__ bias, float* __restrict__ C,
    int M, int N, int K, int epi,
    const float* __restrict__ Z, const float* __restrict__ E,
    int a_split, int a_half)
{
    __shared__ float As[BKT][BM];
    __shared__ float Bs[BKT][BN];

    int tid = threadIdx.x;
    int bm = blockIdx.y * BM;
    int bn = blockIdx.x * BN;

    int lrow = tid >> 1;            // 0..127
    int lcol = (tid & 1) * 4;       // 0 or 4

    int am = bm + lrow;
    int arow_phys = a_split ? (((am >> 9) << 10) + a_half * NS + (am & (NS - 1)))
                            : am;
    const float* Ap = A + arow_phys * K + lcol;
    const float* Wp = W + (bn + lrow) * K + lcol;

    int tr = (tid >> 4) * 8;
    int tc = (tid & 15) * 8;

    float acc[8][8];
#pragma unroll
    for (int i = 0; i < 8; i++)
#pragma unroll
        for (int j = 0; j < 8; j++) acc[i][j] = 0.0f;

    for (int k0 = 0; k0 < K; k0 += BKT) {
        float4 av = *(const float4*)(Ap + k0);
        float4 wv = *(const float4*)(Wp + k0);
        As[lcol + 0][lrow] = av.x; As[lcol + 1][lrow] = av.y;
        As[lcol + 2][lrow] = av.z; As[lcol + 3][lrow] = av.w;
        Bs[lcol + 0][lrow] = wv.x; Bs[lcol + 1][lrow] = wv.y;
        Bs[lcol + 2][lrow] = wv.z; Bs[lcol + 3][lrow] = wv.w;
        __syncthreads();

#pragma unroll
        for (int kk = 0; kk < BKT; kk++) {
            float4 a0 = *(const float4*)&As[kk][tr];
            float4 a1 = *(const float4*)&As[kk][tr + 4];
            float4 b0 = *(const float4*)&Bs[kk][tc];
            float4 b1 = *(const float4*)&Bs[kk][tc + 4];
            float ar[8] = {a0.x, a0.y, a0.z, a0.w, a1.x, a1.y, a1.z, a1.w};
            float br[8] = {b0.x, b0.y, b0.z, b0.w, b1.x, b1.y, b1.z, b1.w};
#pragma unroll
            for (int i = 0; i < 8; i++)
#pragma unroll
                for (int j = 0; j < 8; j++)
                    acc[i][j] += ar[i] * br[j];
        }
        __syncthreads();
    }

#pragma unroll
    for (int i = 0; i < 8; i++) {
        int m = bm + tr + i;
#pragma unroll
        for (int j = 0; j < 8; j++) {
            int n = bn + tc + j;
            float v = acc[i][j] + bias[n];
            if (epi == 0) {
                C[m * N + n] = v;
            } else if (epi == 1) {              // head-major store
                int b = m >> 10, t = m & (S2 - 1);
                int h = n >> 6, hd = n & 63;
                C[((b * NH + h) * S2 + t) * NHD + hd] = v;
            } else if (epi == 2) {              // gelu (tanh approx)
                float x = v;
                float x3 = x * x * x;
                float g = 0.5f * x * (1.0f + tanhf(0.7978845608028654f * (x + 0.044715f * x3)));
                C[m * N + n] = g;
            } else {                            // residual: Z + v * e_resid
                int b = m >> 9;
                float r = E[b * 3 * ND + 2 * ND + n];
                C[m * N + n] = Z[m * N + n] + v * r;
            }
        }
    }
}

// ---------------------------------------------------------------------------
// K4: flash attention.  One block per (b, h, q-tile of 64). BK=32 kv tiles,
// online softmax, everything fp32 in smem. scale = 1/sqrt(64) folded into Q.
// ---------------------------------------------------------------------------
__global__ void __launch_bounds__(256) attn_kernel()
{
    __shared__ float Qs[64][68];
    __shared__ float Ks[32][68];
    __shared__ float Vs[32][68];
    __shared__ float Ss[64][36];
    __shared__ float m_s[64], l_s[64], al_s[64];

    int b = blockIdx.z, h = blockIdx.y, qt = blockIdx.x;
    int tid = threadIdx.x;

    const float* qb = g_qh + ((b * NH + h) * S2 + qt * 64) * NHD;
    const float* kb = g_kh + (b * NH + h) * S2 * NHD;
    const float* vb = g_vh + (b * NH + h) * S2 * NHD;

    for (int i = tid; i < 64 * 64; i += 256)
        Qs[i >> 6][i & 63] = qb[i] * 0.125f;
    if (tid < 64) { m_s[tid] = -1e30f; l_s[tid] = 0.0f; }

    int ty = tid >> 4, tx = tid & 15;
    int r0 = ty * 4;        // 4 q rows per thread
    int cS = tx * 2;        // 2 score cols per thread
    int cO = tx * 4;        // 4 output (hd) cols per thread

    float acc[4][4] = {};

    for (int kt = 0; kt < 32; kt++) {
        __syncthreads();
        for (int i = tid; i < 32 * 64; i += 256) {
            int rr = i >> 6, cc = i & 63;
            Ks[rr][cc] = kb[kt * 2048 + i];
            Vs[rr][cc] = vb[kt * 2048 + i];
        }
        __syncthreads();

        // scores: S = Q K^T  (64 x 32)
        float sacc[4][2] = {};
#pragma unroll
        for (int k4 = 0; k4 < 64; k4 += 4) {
            float4 kv0 = *(const float4*)&Ks[cS][k4];
            float4 kv1 = *(const float4*)&Ks[cS + 1][k4];
#pragma unroll
            for (int ii = 0; ii < 4; ii++) {
                float4 qv = *(const float4*)&Qs[r0 + ii][k4];
                sacc[ii][0] += qv.x * kv0.x + qv.y * kv0.y + qv.z * kv0.z + qv.w * kv0.w;
                sacc[ii][1] += qv.x * kv1.x + qv.y * kv1.y + qv.z * kv1.z + qv.w * kv1.w;
            }
        }
#pragma unroll
        for (int ii = 0; ii < 4; ii++) {
            Ss[r0 + ii][cS]     = sacc[ii][0];
            Ss[r0 + ii][cS + 1] = sacc[ii][1];
        }
        __syncthreads();

        // online softmax stats, one thread per row
        if (tid < 64) {
            float mo = m_s[tid];
            float mx = mo;
#pragma unroll 8
            for (int c = 0; c < 32; c++) mx = fmaxf(mx, Ss[tid][c]);
            float al = __expf(mo - mx);
            float sum = 0.0f;
#pragma unroll 8
            for (int c = 0; c < 32; c++) {
                float p = __expf(Ss[tid][c] - mx);
                Ss[tid][c] = p;
                sum += p;
            }
            m_s[tid] = mx;
            l_s[tid] = l_s[tid] * al + sum;
            al_s[tid] = al;
        }
        __syncthreads();

        // O = O*alpha + P V
        float al4[4];
#pragma unroll
        for (int ii = 0; ii < 4; ii++) al4[ii] = al_s[r0 + ii];
#pragma unroll
        for (int ii = 0; ii < 4; ii++)
#pragma unroll
            for (int jj = 0; jj < 4; jj++) acc[ii][jj] *= al4[ii];

#pragma unroll
        for (int kk = 0; kk < 32; kk++) {
            float4 vv = *(const float4*)&Vs[kk][cO];
#pragma unroll
            for (int ii = 0; ii < 4; ii++) {
                float p = Ss[r0 + ii][kk];
                acc[ii][0] += p * vv.x;
                acc[ii][1] += p * vv.y;
                acc[ii][2] += p * vv.z;
                acc[ii][3] += p * vv.w;
            }
        }
    }

#pragma unroll
    for (int ii = 0; ii < 4; ii++) {
        float inv = 1.0f / l_s[r0 + ii];
        int t = qt * 64 + r0 + ii;
#pragma unroll
        for (int jj = 0; jj < 4; jj++)
            g_o[(b * S2 + t) * ND + h * NHD + cO + jj] = acc[ii][jj] * inv;
    }
}

// ---------------------------------------------------------------------------
// Launch sequence
// ---------------------------------------------------------------------------
extern "C" void kernel_launch(void* const* d_in, const int* in_sizes, int n_in,
                              void* d_out, int out_size)
{
    const float* state_z    = (const float*)d_in[0];
    const float* action_z   = (const float*)d_in[1];
    const float* e          = (const float*)d_in[2];
    const float* qkv_s_w    = (const float*)d_in[3];
    const float* qkv_s_b    = (const float*)d_in[4];
    const float* qkv_a_w    = (const float*)d_in[5];
    const float* qkv_a_b    = (const float*)d_in[6];
    const float* attn_in_w  = (const float*)d_in[7];
    const float* attn_in_b  = (const float*)d_in[8];
    const float* attn_out_w = (const float*)d_in[9];
    const float* attn_out_b = (const float*)d_in[10];
    const float* mw1s       = (const float*)d_in[11];
    const float* mb1s       = (const float*)d_in[12];
    const float* mw2s       = (const float*)d_in[13];
    const float* mb2s       = (const float*)d_in[14];
    const float* mw1a       = (const float*)d_in[15];
    const float* mb1a       = (const float*)d_in[16];
    const float* mw2a       = (const float*)d_in[17];
    const float* mb2a       = (const float*)d_in[18];
    float* out = (float*)d_out;

    float *xs, *xa, *qkvs, *qkva, *q, *k, *v, *qh, *kh, *vh, *o, *y, *h1;
    cudaGetSymbolAddress((void**)&xs,   g_xs);
    cudaGetSymbolAddress((void**)&xa,   g_xa);
    cudaGetSymbolAddress((void**)&qkvs, g_qkvs);
    cudaGetSymbolAddress((void**)&qkva, g_qkva);
    cudaGetSymbolAddress((void**)&q,    g_q);
    cudaGetSymbolAddress((void**)&k,    g_k);
    cudaGetSymbolAddress((void**)&v,    g_v);
    cudaGetSymbolAddress((void**)&qh,   g_qh);
    cudaGetSymbolAddress((void**)&kh,   g_kh);
    cudaGetSymbolAddress((void**)&vh,   g_vh);
    cudaGetSymbolAddress((void**)&o,    g_o);
    cudaGetSymbolAddress((void**)&y,    g_y);
    cudaGetSymbolAddress((void**)&h1,   g_h1);

    // K0: modulation
    modulate_kernel<<<(BSq * ND) / 256, 256>>>(state_z, action_z, e);

    // K1: QKV GEMMs (state, action)
    dim3 g1(D3 / BN, BSq / BM);          // (24, 32)
    sgemm_kernel<<<g1, 256>>>(xs, qkv_s_w, qkv_s_b, qkvs, BSq, D3, ND, 0, nullptr, nullptr, 0, 0);
    sgemm_kernel<<<g1, 256>>>(xa, qkv_a_w, qkv_a_b, qkva, BSq, D3, ND, 0, nullptr, nullptr, 0, 0);

    // K2: RoPE + concat into q/k/v (B, 2S, D)
    rope_kernel<<<(NB * S2 * (ND / 2)) / 256, 256>>>();

    // K3: head projections -> head-major layout
    dim3 g2(ND / BN, BT / BM);           // (8, 64)
    sgemm_kernel<<<g2, 256>>>(q, attn_in_w,               attn_in_b,          qh, BT, ND, ND, 1, nullptr, nullptr, 0, 0);
    sgemm_kernel<<<g2, 256>>>(k, attn_in_w + ND * ND,     attn_in_b + ND,     kh, BT, ND, ND, 1, nullptr, nullptr, 0, 0);
    sgemm_kernel<<<g2, 256>>>(v, attn_in_w + 2 * ND * ND, attn_in_b + 2 * ND, vh, BT, ND, ND, 1, nullptr, nullptr, 0, 0);

    // K4: attention
    dim3 ga(S2 / 64, NH, NB);            // (16, 16, 8)
    attn_kernel<<<ga, 256>>>();

    // K5: output projection
    sgemm_kernel<<<g2, 256>>>(o, attn_out_w, attn_out_b, y, BT, ND, ND, 0, nullptr, nullptr, 0, 0);

    // K6/K7: MLPs with gated residual (state branch, then action branch)
    dim3 g3(D4 / BN, BSq / BM);          // (32, 32)
    dim3 g4(ND / BN, BSq / BM);          // (8, 32)
    sgemm_kernel<<<g3, 256>>>(y,  mw1s, mb1s, h1,               BSq, D4, ND, 2, nullptr,  nullptr, 1, 0);
    sgemm_kernel<<<g4, 256>>>(h1, mw2s, mb2s, out,              BSq, ND, D4, 3, state_z,  e,       0, 0);
    sgemm_kernel<<<g3, 256>>>(y,  mw1a, mb1a, h1,               BSq, D4, ND, 2, nullptr,  nullptr, 1, 1);
    sgemm_kernel<<<g4, 256>>>(h1, mw2a, mb2a, out + BSq * ND,   BSq, ND, D4, 3, action_z, e,       0, 0);
}

// round 3
// speedup vs baseline: 3.4059x; 3.4059x over previous
#include <cuda_runtime.h>
#include <cuda_bf16.h>
#include <math.h>
#include <stdint.h>

#define NB   8
#define NS   512
#define ND   1024
#define NH   16
#define NHD  64
#define S2   1024
#define BSq  4096
#define BT   8192
#define D3   3072
#define D4   4096

// ---------------------------------------------------------------------------
// Scratch (device globals)
// ---------------------------------------------------------------------------
__device__ float g_qkvs[BSq * D3];
__device__ float g_qkva[BSq * D3];
__device__ float g_qh  [BT * ND];
__device__ float g_kh  [BT * ND];
__device__ float g_vh  [BT * ND];

__device__ __nv_bfloat16 g_xsb[BSq * ND];
__device__ __nv_bfloat16 g_xab[BSq * ND];
__device__ __nv_bfloat16 g_qb [BT * ND];
__device__ __nv_bfloat16 g_kb [BT * ND];
__device__ __nv_bfloat16 g_vb [BT * ND];
__device__ __nv_bfloat16 g_ob [BT * ND];
__device__ __nv_bfloat16 g_yb [BT * ND];
__device__ __nv_bfloat16 g_h1b[BSq * D4];

// bf16 weight copies
__device__ __nv_bfloat16 g_wqs[D3 * ND];
__device__ __nv_bfloat16 g_wqa[D3 * ND];
__device__ __nv_bfloat16 g_wai[D3 * ND];
__device__ __nv_bfloat16 g_wao[ND * ND];
__device__ __nv_bfloat16 g_w1s[D4 * ND];
__device__ __nv_bfloat16 g_w2s[ND * D4];
__device__ __nv_bfloat16 g_w1a[D4 * ND];
__device__ __nv_bfloat16 g_w2a[ND * D4];

// ---------------------------------------------------------------------------
// PTX helpers (sm_80-era only; no 'a'-suffix features)
// ---------------------------------------------------------------------------
__device__ __forceinline__ uint32_t smem_u32(const void* p) {
    uint32_t a;
    asm("{ .reg .u64 t; cvta.to.shared.u64 t, %1; cvt.u32.u64 %0, t; }"
        : "=r"(a) : "l"(p));
    return a;
}

__device__ __forceinline__ void cp16(uint32_t dst, const void* src) {
    asm volatile("cp.async.cg.shared.global [%0], [%1], 16;"
                 :: "r"(dst), "l"(src) : "memory");
}

__device__ __forceinline__ void ldm4(uint32_t addr, uint32_t* r) {
    asm volatile("ldmatrix.sync.aligned.m8n8.x4.shared.b16 {%0,%1,%2,%3}, [%4];"
                 : "=r"(r[0]), "=r"(r[1]), "=r"(r[2]), "=r"(r[3]) : "r"(addr));
}

__device__ __forceinline__ void mma16816(float* c, const uint32_t* a, const uint32_t* b) {
    asm volatile(
        "mma.sync.aligned.m16n8k16.row.col.f32.bf16.bf16.f32 "
        "{%0,%1,%2,%3}, {%4,%5,%6,%7}, {%8,%9}, {%0,%1,%2,%3};"
        : "+f"(c[0]), "+f"(c[1]), "+f"(c[2]), "+f"(c[3])
        : "r"(a[0]), "r"(a[1]), "r"(a[2]), "r"(a[3]), "r"(b[0]), "r"(b[1]));
}

// ---------------------------------------------------------------------------
// Elementwise kernels
// ---------------------------------------------------------------------------
__global__ void f2bf_kernel(const float* __restrict__ s, __nv_bfloat16* __restrict__ d, int n) {
    int i = (blockIdx.x * blockDim.x + threadIdx.x) * 4;
    if (i >= n) return;
    float4 v = *(const float4*)(s + i);
    *(__nv_bfloat162*)(d + i)     = __floats2bfloat162_rn(v.x, v.y);
    *(__nv_bfloat162*)(d + i + 2) = __floats2bfloat162_rn(v.z, v.w);
}

__global__ void modulate_kernel(const float* __restrict__ sz,
                                const float* __restrict__ az,
                                const float* __restrict__ e) {
    int idx = blockIdx.x * blockDim.x + threadIdx.x;
    if (idx >= BSq * ND) return;
    int b = idx >> 19;
    int k = idx & (ND - 1);
    const float* eb = e + b * 3 * ND;
    float sc = 1.0f + eb[ND + k];
    float sh = eb[k];
    g_xsb[idx] = __float2bfloat16(sc * sz[idx] + sh);
    g_xab[idx] = __float2bfloat16(sc * az[idx] + sh);
}

__global__ void rope_kernel() {
    int idx = blockIdx.x * blockDim.x + threadIdx.x;
    if (idx >= NB * S2 * (ND / 2)) return;
    int i = idx & 511;
    int t = (idx >> 9) & (S2 - 1);
    int b = idx >> 19;
    const float* src;
    int s;
    if (t < NS) { src = g_qkvs; s = t; }
    else        { src = g_qkva; s = t - NS; }
    const float* row = src + (size_t)(b * NS + s) * D3;

    float inv = expf(-6.238324625039508f * (float)(2 * i) * (1.0f / 1024.0f));
    float th  = (float)s * inv;
    float sn, c;
    sincosf(th, &sn, &c);

    int dst = (b * S2 + t) * ND + 2 * i;
    {
        float xe = row[2 * i], xo = row[2 * i + 1];
        *(__nv_bfloat162*)&g_qb[dst] = __floats2bfloat162_rn(xe * c - xo * sn, xe * sn + xo * c);
    }
    {
        float xe = row[ND + 2 * i], xo = row[ND + 2 * i + 1];
        *(__nv_bfloat162*)&g_kb[dst] = __floats2bfloat162_rn(xe * c - xo * sn, xe * sn + xo * c);
    }
    *(__nv_bfloat162*)&g_vb[dst] = __floats2bfloat162_rn(row[2 * ND + 2 * i], row[2 * ND + 2 * i + 1]);
}

// ---------------------------------------------------------------------------
// bf16 GEMM via mma.sync:  C[M,N] = A[M,K] @ W[N,K]^T + bias, fused epilogues
//   EPI 0: fp32 plain   1: fp32 head-major   2: gelu->bf16   3: residual fp32
//   EPI 4: bf16 plain
// 128x128 block, BK=32, 3-stage cp.async pipeline, 8 warps (2x4), 64x32/warp.
// Smem rows padded to 80B -> conflict-free ldmatrix.
// ---------------------------------------------------------------------------
#define ROWB   80
#define STG    (128 * ROWB)        // 10240 B per operand-stage
#define STAGES 3
#define DSMEM_BYTES (2 * STAGES * STG)   // 61440

template<int EPI>
__global__ void __launch_bounds__(256) gemm_mma(
    const __nv_bfloat16* __restrict__ A, const __nv_bfloat16* __restrict__ W,
    const float* __restrict__ bias, void* __restrict__ Cout,
    int M, int N, int K,
    const float* __restrict__ Z, const float* __restrict__ E,
    int a_split, int a_half)
{
    extern __shared__ char sm_[];
    const uint32_t Ab = smem_u32(sm_);
    const uint32_t Bb = Ab + STAGES * STG;

    int tid = threadIdx.x, lane = tid & 31, wid = tid >> 5;
    int wm = wid & 1, wn = wid >> 1;
    int bm = blockIdx.y * 128, bn = blockIdx.x * 128;

    // --- global load geometry: each thread 16B x (2 rows A + 2 rows B) per stage
    int lr = tid >> 2, lc = tid & 3;
    int am0 = bm + lr, am1 = bm + lr + 64;
    int ar0 = a_split ? (((am0 >> 9) << 10) + a_half * NS + (am0 & (NS - 1))) : am0;
    int ar1 = a_split ? (((am1 >> 9) << 10) + a_half * NS + (am1 & (NS - 1))) : am1;
    const __nv_bfloat16* Ag0 = A + (size_t)ar0 * K + lc * 8;
    const __nv_bfloat16* Ag1 = A + (size_t)ar1 * K + lc * 8;
    const __nv_bfloat16* Wg0 = W + (size_t)(bn + lr) * K + lc * 8;
    const __nv_bfloat16* Wg1 = W + (size_t)(bn + lr + 64) * K + lc * 8;
    uint32_t dst0 = (uint32_t)(lr * ROWB + lc * 16);
    uint32_t dst1 = dst0 + 64 * ROWB;

    // --- compute-side smem fragment offsets
    uint32_t aoff = (uint32_t)((wm * 64 + (lane & 15)) * ROWB + (lane >> 4) * 16);
    uint32_t boff = (uint32_t)((wn * 32 + (lane >> 4) * 8 + (lane & 7)) * ROWB
                               + ((lane >> 3) & 1) * 16);

    float acc[4][4][4] = {};
    const int NK = K >> 5;

    // prologue
#pragma unroll
    for (int s = 0; s < STAGES - 1; s++) {
        uint32_t a = Ab + s * STG, b = Bb + s * STG;
        int ke = s * 32;
        cp16(a + dst0, Ag0 + ke); cp16(a + dst1, Ag1 + ke);
        cp16(b + dst0, Wg0 + ke); cp16(b + dst1, Wg1 + ke);
        asm volatile("cp.async.commit_group;" ::: "memory");
    }

    for (int kt = 0; kt < NK; kt++) {
        asm volatile("cp.async.wait_group %0;" :: "n"(STAGES - 2) : "memory");
        __syncthreads();

        int s = kt % STAGES;
        uint32_t a0 = Ab + s * STG + aoff;
        uint32_t b0 = Bb + s * STG + boff;
#pragma unroll
        for (int ks = 0; ks < 2; ks++) {
            uint32_t af[4][4], bf[2][4];
#pragma unroll
            for (int mf = 0; mf < 4; mf++) ldm4(a0 + mf * 16 * ROWB + ks * 32, af[mf]);
#pragma unroll
            for (int nn = 0; nn < 2; nn++) ldm4(b0 + nn * 16 * ROWB + ks * 32, bf[nn]);
#pragma unroll
            for (int mf = 0; mf < 4; mf++)
#pragma unroll
                for (int nf = 0; nf < 4; nf++)
                    mma16816(acc[mf][nf], af[mf], &bf[nf >> 1][(nf & 1) * 2]);
        }
        __syncthreads();

        int j = kt + STAGES - 1;
        if (j < NK) {
            int sj = j % STAGES;
            uint32_t a = Ab + sj * STG, b = Bb + sj * STG;
            int ke = j * 32;
            cp16(a + dst0, Ag0 + ke); cp16(a + dst1, Ag1 + ke);
            cp16(b + dst0, Wg0 + ke); cp16(b + dst1, Wg1 + ke);
        }
        asm volatile("cp.async.commit_group;" ::: "memory");
    }

    // --- epilogue: fragments -> global, fused bias + transform
    int gr = lane >> 2, gc = (lane & 3) * 2;
#pragma unroll
    for (int mf = 0; mf < 4; mf++) {
#pragma unroll
        for (int nf = 0; nf < 4; nf++) {
            float* c = acc[mf][nf];
            int n  = bn + wn * 32 + nf * 8 + gc;
            int m0 = bm + wm * 64 + mf * 16 + gr;
#pragma unroll
            for (int half = 0; half < 2; half++) {
                int m = m0 + half * 8;
                float v0 = c[half * 2]     + bias[n];
                float v1 = c[half * 2 + 1] + bias[n + 1];
                if (EPI == 0) {
                    *(float2*)((float*)Cout + (size_t)m * N + n) = make_float2(v0, v1);
                } else if (EPI == 1) {
                    int b = m >> 10, t = m & (S2 - 1), h = n >> 6;
                    float* dst = (float*)Cout + ((size_t)(b * NH + h) * S2 + t) * NHD + (n & 63);
                    *(float2*)dst = make_float2(v0, v1);
                } else if (EPI == 2) {
                    float x = v0;
                    float gx = 0.5f * x * (1.0f + tanhf(0.7978845608028654f * (x + 0.044715f * x * x * x)));
                    x = v1;
                    float gy = 0.5f * x * (1.0f + tanhf(0.7978845608028654f * (x + 0.044715f * x * x * x)));
                    *(__nv_bfloat162*)((__nv_bfloat16*)Cout + (size_t)m * N + n) =
                        __floats2bfloat162_rn(gx, gy);
                } else if (EPI == 3) {
                    int b = m >> 9;
                    const float* ep = E + (size_t)b * 3 * ND + 2 * ND + n;
                    const float* zp = Z + (size_t)m * N + n;
                    *(float2*)((float*)Cout + (size_t)m * N + n) =
                        make_float2(zp[0] + v0 * ep[0], zp[1] + v1 * ep[1]);
                } else {
                    *(__nv_bfloat162*)((__nv_bfloat16*)Cout + (size_t)m * N + n) =
                        __floats2bfloat162_rn(v0, v1);
                }
            }
        }
    }
}

// ---------------------------------------------------------------------------
// Flash attention (fp32 SIMT, known-correct), output stored as bf16
// ---------------------------------------------------------------------------
__global__ void __launch_bounds__(256) attn_kernel()
{
    __shared__ float Qs[64][68];
    __shared__ float Ks[32][68];
    __shared__ float Vs[32][68];
    __shared__ float Ss[64][36];
    __shared__ float m_s[64], l_s[64], al_s[64];

    int b = blockIdx.z, h = blockIdx.y, qt = blockIdx.x;
    int tid = threadIdx.x;

    const float* qb = g_qh + ((size_t)(b * NH + h) * S2 + qt * 64) * NHD;
    const float* kb = g_kh + (size_t)(b * NH + h) * S2 * NHD;
    const float* vb = g_vh + (size_t)(b * NH + h) * S2 * NHD;

    for (int i = tid; i < 64 * 64; i += 256)
        Qs[i >> 6][i & 63] = qb[i] * 0.125f;
    if (tid < 64) { m_s[tid] = -1e30f; l_s[tid] = 0.0f; }

    int ty = tid >> 4, tx = tid & 15;
    int r0 = ty * 4;
    int cS = tx * 2;
    int cO = tx * 4;

    float acc[4][4] = {};

    for (int kt = 0; kt < 32; kt++) {
        __syncthreads();
        for (int i = tid; i < 32 * 64; i += 256) {
            int rr = i >> 6, cc = i & 63;
            Ks[rr][cc] = kb[kt * 2048 + i];
            Vs[rr][cc] = vb[kt * 2048 + i];
        }
        __syncthreads();

        float sacc[4][2] = {};
#pragma unroll
        for (int k4 = 0; k4 < 64; k4 += 4) {
            float4 kv0 = *(const float4*)&Ks[cS][k4];
            float4 kv1 = *(const float4*)&Ks[cS + 1][k4];
#pragma unroll
            for (int ii = 0; ii < 4; ii++) {
                float4 qv = *(const float4*)&Qs[r0 + ii][k4];
                sacc[ii][0] += qv.x * kv0.x + qv.y * kv0.y + qv.z * kv0.z + qv.w * kv0.w;
                sacc[ii][1] += qv.x * kv1.x + qv.y * kv1.y + qv.z * kv1.z + qv.w * kv1.w;
            }
        }
#pragma unroll
        for (int ii = 0; ii < 4; ii++) {
            Ss[r0 + ii][cS]     = sacc[ii][0];
            Ss[r0 + ii][cS + 1] = sacc[ii][1];
        }
        __syncthreads();

        if (tid < 64) {
            float mo = m_s[tid];
            float mx = mo;
#pragma unroll 8
            for (int c = 0; c < 32; c++) mx = fmaxf(mx, Ss[tid][c]);
            float al = __expf(mo - mx);
            float sum = 0.0f;
#pragma unroll 8
            for (int c = 0; c < 32; c++) {
                float p = __expf(Ss[tid][c] - mx);
                Ss[tid][c] = p;
                sum += p;
            }
            m_s[tid] = mx;
            l_s[tid] = l_s[tid] * al + sum;
            al_s[tid] = al;
        }
        __syncthreads();

        float al4[4];
#pragma unroll
        for (int ii = 0; ii < 4; ii++) al4[ii] = al_s[r0 + ii];
#pragma unroll
        for (int ii = 0; ii < 4; ii++)
#pragma unroll
            for (int jj = 0; jj < 4; jj++) acc[ii][jj] *= al4[ii];

#pragma unroll
        for (int kk = 0; kk < 32; kk++) {
            float4 vv = *(const float4*)&Vs[kk][cO];
#pragma unroll
            for (int ii = 0; ii < 4; ii++) {
                float p = Ss[r0 + ii][kk];
                acc[ii][0] += p * vv.x;
                acc[ii][1] += p * vv.y;
                acc[ii][2] += p * vv.z;
                acc[ii][3] += p * vv.w;
            }
        }
    }

#pragma unroll
    for (int ii = 0; ii < 4; ii++) {
        float inv = 1.0f / l_s[r0 + ii];
        int t = qt * 64 + r0 + ii;
        __nv_bfloat16* dst = g_ob + ((size_t)(b * S2 + t) * ND + h * NHD + cO);
        *(__nv_bfloat162*)(dst)     = __floats2bfloat162_rn(acc[ii][0] * inv, acc[ii][1] * inv);
        *(__nv_bfloat162*)(dst + 2) = __floats2bfloat162_rn(acc[ii][2] * inv, acc[ii][3] * inv);
    }
}

// ---------------------------------------------------------------------------
// Launch sequence
// ---------------------------------------------------------------------------
extern "C" void kernel_launch(void* const* d_in, const int* in_sizes, int n_in,
                              void* d_out, int out_size)
{
    const float* state_z    = (const float*)d_in[0];
    const float* action_z   = (const float*)d_in[1];
    const float* e          = (const float*)d_in[2];
    const float* qkv_s_w    = (const float*)d_in[3];
    const float* qkv_s_b    = (const float*)d_in[4];
    const float* qkv_a_w    = (const float*)d_in[5];
    const float* qkv_a_b    = (const float*)d_in[6];
    const float* attn_in_w  = (const float*)d_in[7];
    const float* attn_in_b  = (const float*)d_in[8];
    const float* attn_out_w = (const float*)d_in[9];
    const float* attn_out_b = (const float*)d_in[10];
    const float* mw1s       = (const float*)d_in[11];
    const float* mb1s       = (const float*)d_in[12];
    const float* mw2s       = (const float*)d_in[13];
    const float* mb2s       = (const float*)d_in[14];
    const float* mw1a       = (const float*)d_in[15];
    const float* mb1a       = (const float*)d_in[16];
    const float* mw2a       = (const float*)d_in[17];
    const float* mb2a       = (const float*)d_in[18];
    float* out = (float*)d_out;

    float *qkvs, *qkva, *qh, *kh, *vh;
    __nv_bfloat16 *xsb, *xab, *qb, *kb, *vb, *ob, *yb, *h1b;
    __nv_bfloat16 *wqs, *wqa, *wai, *wao, *w1s, *w2s, *w1a, *w2a;
    cudaGetSymbolAddress((void**)&qkvs, g_qkvs);
    cudaGetSymbolAddress((void**)&qkva, g_qkva);
    cudaGetSymbolAddress((void**)&qh,   g_qh);
    cudaGetSymbolAddress((void**)&kh,   g_kh);
    cudaGetSymbolAddress((void**)&vh,   g_vh);
    cudaGetSymbolAddress((void**)&xsb,  g_xsb);
    cudaGetSymbolAddress((void**)&xab,  g_xab);
    cudaGetSymbolAddress((void**)&qb,   g_qb);
    cudaGetSymbolAddress((void**)&kb,   g_kb);
    cudaGetSymbolAddress((void**)&vb,   g_vb);
    cudaGetSymbolAddress((void**)&ob,   g_ob);
    cudaGetSymbolAddress((void**)&yb,   g_yb);
    cudaGetSymbolAddress((void**)&h1b,  g_h1b);
    cudaGetSymbolAddress((void**)&wqs,  g_wqs);
    cudaGetSymbolAddress((void**)&wqa,  g_wqa);
    cudaGetSymbolAddress((void**)&wai,  g_wai);
    cudaGetSymbolAddress((void**)&wao,  g_wao);
    cudaGetSymbolAddress((void**)&w1s,  g_w1s);
    cudaGetSymbolAddress((void**)&w2s,  g_w2s);
    cudaGetSymbolAddress((void**)&w1a,  g_w1a);
    cudaGetSymbolAddress((void**)&w2a,  g_w2a);

    cudaFuncSetAttribute(gemm_mma<0>, cudaFuncAttributeMaxDynamicSharedMemorySize, DSMEM_BYTES);
    cudaFuncSetAttribute(gemm_mma<1>, cudaFuncAttributeMaxDynamicSharedMemorySize, DSMEM_BYTES);
    cudaFuncSetAttribute(gemm_mma<2>, cudaFuncAttributeMaxDynamicSharedMemorySize, DSMEM_BYTES);
    cudaFuncSetAttribute(gemm_mma<3>, cudaFuncAttributeMaxDynamicSharedMemorySize, DSMEM_BYTES);
    cudaFuncSetAttribute(gemm_mma<4>, cudaFuncAttributeMaxDynamicSharedMemorySize, DSMEM_BYTES);

    // weight conversion fp32 -> bf16
    {
        struct { const float* s; __nv_bfloat16* d; int n; } cv[8] = {
            {qkv_s_w, wqs, D3 * ND}, {qkv_a_w, wqa, D3 * ND},
            {attn_in_w, wai, D3 * ND}, {attn_out_w, wao, ND * ND},
            {mw1s, w1s, D4 * ND}, {mw2s, w2s, ND * D4},
            {mw1a, w1a, D4 * ND}, {mw2a, w2a, ND * D4},
        };
        for (int i = 0; i < 8; i++)
            f2bf_kernel<<<(cv[i].n / 4 + 255) / 256, 256>>>(cv[i].s, cv[i].d, cv[i].n);
    }

    // modulation -> bf16 activations
    modulate_kernel<<<(BSq * ND) / 256, 256>>>(state_z, action_z, e);

    // QKV GEMMs
    dim3 g1(D3 / 128, BSq / 128);
    gemm_mma<0><<<g1, 256, DSMEM_BYTES>>>(xsb, wqs, qkv_s_b, qkvs, BSq, D3, ND, nullptr, nullptr, 0, 0);
    gemm_mma<0><<<g1, 256, DSMEM_BYTES>>>(xab, wqa, qkv_a_b, qkva, BSq, D3, ND, nullptr, nullptr, 0, 0);

    // RoPE + concat (bf16 out)
    rope_kernel<<<(NB * S2 * (ND / 2)) / 256, 256>>>();

    // head projections -> fp32 head-major
    dim3 g2(ND / 128, BT / 128);
    gemm_mma<1><<<g2, 256, DSMEM_BYTES>>>(qb, wai,               attn_in_b,          qh, BT, ND, ND, nullptr, nullptr, 0, 0);
    gemm_mma<1><<<g2, 256, DSMEM_BYTES>>>(kb, wai + ND * ND,     attn_in_b + ND,     kh, BT, ND, ND, nullptr, nullptr, 0, 0);
    gemm_mma<1><<<g2, 256, DSMEM_BYTES>>>(vb, wai + 2 * ND * ND, attn_in_b + 2 * ND, vh, BT, ND, ND, nullptr, nullptr, 0, 0);

    // attention
    dim3 ga(S2 / 64, NH, NB);
    attn_kernel<<<ga, 256>>>();

    // output projection -> bf16
    gemm_mma<4><<<g2, 256, DSMEM_BYTES>>>(ob, wao, attn_out_b, yb, BT, ND, ND, nullptr, nullptr, 0, 0);

    // MLPs with gated residual
    dim3 g3(D4 / 128, BSq / 128);
    dim3 g4(ND / 128, BSq / 128);
    gemm_mma<2><<<g3, 256, DSMEM_BYTES>>>(yb,  w1s, mb1s, h1b,            BSq, D4, ND, nullptr,  nullptr, 1, 0);
    gemm_mma<3><<<g4, 256, DSMEM_BYTES>>>(h1b, w2s, mb2s, out,            BSq, ND, D4, state_z,  e,       0, 0);
    gemm_mma<2><<<g3, 256, DSMEM_BYTES>>>(yb,  w1a, mb1a, h1b,            BSq, D4, ND, nullptr,  nullptr, 1, 1);
    gemm_mma<3><<<g4, 256, DSMEM_BYTES>>>(h1b, w2a, mb2a, out + (size_t)BSq * ND, BSq, ND, D4, action_z, e, 0, 0);
}

// round 4
// speedup vs baseline: 6.4538x; 1.8949x over previous
#include <cuda_runtime.h>
#include <cuda_bf16.h>
#include <cuda_fp16.h>
#include <math.h>
#include <stdint.h>

#define NB   8
#define NS   512
#define ND   1024
#define NH   16
#define NHD  64
#define S2   1024
#define BSq  4096
#define BT   8192
#define D3   3072
#define D4   4096

// ---------------------------------------------------------------------------
// Scratch (device globals)
// ---------------------------------------------------------------------------
__device__ float g_qkvs[BSq * D3];
__device__ float g_qkva[BSq * D3];

__device__ __half g_qhh[BT * ND];   // fp16 head-major (B,H,S2,HD)
__device__ __half g_khh[BT * ND];
__device__ __half g_vhh[BT * ND];

__device__ __nv_bfloat16 g_xsb[BSq * ND];
__device__ __nv_bfloat16 g_xab[BSq * ND];
__device__ __nv_bfloat16 g_qb [BT * ND];
__device__ __nv_bfloat16 g_kb [BT * ND];
__device__ __nv_bfloat16 g_vb [BT * ND];
__device__ __nv_bfloat16 g_ob [BT * ND];
__device__ __nv_bfloat16 g_yb [BT * ND];
__device__ __nv_bfloat16 g_h1b[BSq * D4];

// bf16 weight copies
__device__ __nv_bfloat16 g_wqs[D3 * ND];
__device__ __nv_bfloat16 g_wqa[D3 * ND];
__device__ __nv_bfloat16 g_wai[D3 * ND];
__device__ __nv_bfloat16 g_wao[ND * ND];
__device__ __nv_bfloat16 g_w1s[D4 * ND];
__device__ __nv_bfloat16 g_w2s[ND * D4];
__device__ __nv_bfloat16 g_w1a[D4 * ND];
__device__ __nv_bfloat16 g_w2a[ND * D4];

// ---------------------------------------------------------------------------
// PTX helpers (sm_80-era only)
// ---------------------------------------------------------------------------
__device__ __forceinline__ uint32_t smem_u32(const void* p) {
    uint32_t a;
    asm("{ .reg .u64 t; cvta.to.shared.u64 t, %1; cvt.u32.u64 %0, t; }"
        : "=r"(a) : "l"(p));
    return a;
}

__device__ __forceinline__ void cp16(uint32_t dst, const void* src) {
    asm volatile("cp.async.cg.shared.global [%0], [%1], 16;"
                 :: "r"(dst), "l"(src) : "memory");
}

__device__ __forceinline__ void ldm4(uint32_t addr, uint32_t* r) {
    asm volatile("ldmatrix.sync.aligned.m8n8.x4.shared.b16 {%0,%1,%2,%3}, [%4];"
                 : "=r"(r[0]), "=r"(r[1]), "=r"(r[2]), "=r"(r[3]) : "r"(addr));
}

__device__ __forceinline__ void ldm4t(uint32_t addr, uint32_t* r) {
    asm volatile("ldmatrix.sync.aligned.m8n8.x4.trans.shared.b16 {%0,%1,%2,%3}, [%4];"
                 : "=r"(r[0]), "=r"(r[1]), "=r"(r[2]), "=r"(r[3]) : "r"(addr));
}

__device__ __forceinline__ void mma16816(float* c, const uint32_t* a, const uint32_t* b) {
    asm volatile(
        "mma.sync.aligned.m16n8k16.row.col.f32.bf16.bf16.f32 "
        "{%0,%1,%2,%3}, {%4,%5,%6,%7}, {%8,%9}, {%0,%1,%2,%3};"
        : "+f"(c[0]), "+f"(c[1]), "+f"(c[2]), "+f"(c[3])
        : "r"(a[0]), "r"(a[1]), "r"(a[2]), "r"(a[3]), "r"(b[0]), "r"(b[1]));
}

__device__ __forceinline__ void mma16816h(float* c, const uint32_t* a, const uint32_t* b) {
    asm volatile(
        "mma.sync.aligned.m16n8k16.row.col.f32.f16.f16.f32 "
        "{%0,%1,%2,%3}, {%4,%5,%6,%7}, {%8,%9}, {%0,%1,%2,%3};"
        : "+f"(c[0]), "+f"(c[1]), "+f"(c[2]), "+f"(c[3])
        : "r"(a[0]), "r"(a[1]), "r"(a[2]), "r"(a[3]), "r"(b[0]), "r"(b[1]));
}

__device__ __forceinline__ uint32_t h2pack(float a, float b) {
    __half2 t = __floats2half2_rn(a, b);
    return *reinterpret_cast<uint32_t*>(&t);
}

// ---------------------------------------------------------------------------
// Elementwise kernels
// ---------------------------------------------------------------------------
__global__ void f2bf_kernel(const float* __restrict__ s, __nv_bfloat16* __restrict__ d, int n) {
    int i = (blockIdx.x * blockDim.x + threadIdx.x) * 4;
    if (i >= n) return;
    float4 v = *(const float4*)(s + i);
    *(__nv_bfloat162*)(d + i)     = __floats2bfloat162_rn(v.x, v.y);
    *(__nv_bfloat162*)(d + i + 2) = __floats2bfloat162_rn(v.z, v.w);
}

__global__ void modulate_kernel(const float* __restrict__ sz,
                                const float* __restrict__ az,
                                const float* __restrict__ e) {
    int idx = blockIdx.x * blockDim.x + threadIdx.x;
    if (idx >= BSq * ND) return;
    int b = idx >> 19;
    int k = idx & (ND - 1);
    const float* eb = e + b * 3 * ND;
    float sc = 1.0f + eb[ND + k];
    float sh = eb[k];
    g_xsb[idx] = __float2bfloat16(sc * sz[idx] + sh);
    g_xab[idx] = __float2bfloat16(sc * az[idx] + sh);
}

__global__ void rope_kernel() {
    int idx = blockIdx.x * blockDim.x + threadIdx.x;
    if (idx >= NB * S2 * (ND / 2)) return;
    int i = idx & 511;
    int t = (idx >> 9) & (S2 - 1);
    int b = idx >> 19;
    const float* src;
    int s;
    if (t < NS) { src = g_qkvs; s = t; }
    else        { src = g_qkva; s = t - NS; }
    const float* row = src + (size_t)(b * NS + s) * D3;

    float inv = expf(-6.238324625039508f * (float)(2 * i) * (1.0f / 1024.0f));
    float th  = (float)s * inv;
    float sn, c;
    sincosf(th, &sn, &c);

    int dst = (b * S2 + t) * ND + 2 * i;
    {
        float xe = row[2 * i], xo = row[2 * i + 1];
        *(__nv_bfloat162*)&g_qb[dst] = __floats2bfloat162_rn(xe * c - xo * sn, xe * sn + xo * c);
    }
    {
        float xe = row[ND + 2 * i], xo = row[ND + 2 * i + 1];
        *(__nv_bfloat162*)&g_kb[dst] = __floats2bfloat162_rn(xe * c - xo * sn, xe * sn + xo * c);
    }
    *(__nv_bfloat162*)&g_vb[dst] = __floats2bfloat162_rn(row[2 * ND + 2 * i], row[2 * ND + 2 * i + 1]);
}

// ---------------------------------------------------------------------------
// bf16 GEMM via mma.sync:  C[M,N] = A[M,K] @ W[N,K]^T + bias, fused epilogues
//   EPI 0: fp32 plain   2: gelu->bf16   3: residual fp32   4: bf16 plain
//   EPI 6: fp16 head-major (B,H,S2,HD)
// ---------------------------------------------------------------------------
#define ROWB   80
#define STG    (128 * ROWB)
#define STAGES 3
#define DSMEM_BYTES (2 * STAGES * STG)

template<int EPI>
__global__ void __launch_bounds__(256) gemm_mma(
    const __nv_bfloat16* __restrict__ A, const __nv_bfloat16* __restrict__ W,
    const float* __restrict__ bias, void* __restrict__ Cout,
    int M, int N, int K,
    const float* __restrict__ Z, const float* __restrict__ E,
    int a_split, int a_half)
{
    extern __shared__ char sm_[];
    const uint32_t Ab = smem_u32(sm_);
    const uint32_t Bb = Ab + STAGES * STG;

    int tid = threadIdx.x, lane = tid & 31, wid = tid >> 5;
    int wm = wid & 1, wn = wid >> 1;
    int bm = blockIdx.y * 128, bn = blockIdx.x * 128;

    int lr = tid >> 2, lc = tid & 3;
    int am0 = bm + lr, am1 = bm + lr + 64;
    int ar0 = a_split ? (((am0 >> 9) << 10) + a_half * NS + (am0 & (NS - 1))) : am0;
    int ar1 = a_split ? (((am1 >> 9) << 10) + a_half * NS + (am1 & (NS - 1))) : am1;
    const __nv_bfloat16* Ag0 = A + (size_t)ar0 * K + lc * 8;
    const __nv_bfloat16* Ag1 = A + (size_t)ar1 * K + lc * 8;
    const __nv_bfloat16* Wg0 = W + (size_t)(bn + lr) * K + lc * 8;
    const __nv_bfloat16* Wg1 = W + (size_t)(bn + lr + 64) * K + lc * 8;
    uint32_t dst0 = (uint32_t)(lr * ROWB + lc * 16);
    uint32_t dst1 = dst0 + 64 * ROWB;

    uint32_t aoff = (uint32_t)((wm * 64 + (lane & 15)) * ROWB + (lane >> 4) * 16);
    uint32_t boff = (uint32_t)((wn * 32 + (lane >> 4) * 8 + (lane & 7)) * ROWB
                               + ((lane >> 3) & 1) * 16);

    float acc[4][4][4] = {};
    const int NK = K >> 5;

#pragma unroll
    for (int s = 0; s < STAGES - 1; s++) {
        uint32_t a = Ab + s * STG, b = Bb + s * STG;
        int ke = s * 32;
        cp16(a + dst0, Ag0 + ke); cp16(a + dst1, Ag1 + ke);
        cp16(b + dst0, Wg0 + ke); cp16(b + dst1, Wg1 + ke);
        asm volatile("cp.async.commit_group;" ::: "memory");
    }

    for (int kt = 0; kt < NK; kt++) {
        asm volatile("cp.async.wait_group %0;" :: "n"(STAGES - 2) : "memory");
        __syncthreads();

        int s = kt % STAGES;
        uint32_t a0 = Ab + s * STG + aoff;
        uint32_t b0 = Bb + s * STG + boff;
#pragma unroll
        for (int ks = 0; ks < 2; ks++) {
            uint32_t af[4][4], bf[2][4];
#pragma unroll
            for (int mf = 0; mf < 4; mf++) ldm4(a0 + mf * 16 * ROWB + ks * 32, af[mf]);
#pragma unroll
            for (int nn = 0; nn < 2; nn++) ldm4(b0 + nn * 16 * ROWB + ks * 32, bf[nn]);
#pragma unroll
            for (int mf = 0; mf < 4; mf++)
#pragma unroll
                for (int nf = 0; nf < 4; nf++)
                    mma16816(acc[mf][nf], af[mf], &bf[nf >> 1][(nf & 1) * 2]);
        }
        __syncthreads();

        int j = kt + STAGES - 1;
        if (j < NK) {
            int sj = j % STAGES;
            uint32_t a = Ab + sj * STG, b = Bb + sj * STG;
            int ke = j * 32;
            cp16(a + dst0, Ag0 + ke); cp16(a + dst1, Ag1 + ke);
            cp16(b + dst0, Wg0 + ke); cp16(b + dst1, Wg1 + ke);
        }
        asm volatile("cp.async.commit_group;" ::: "memory");
    }

    int gr = lane >> 2, gc = (lane & 3) * 2;
#pragma unroll
    for (int mf = 0; mf < 4; mf++) {
#pragma unroll
        for (int nf = 0; nf < 4; nf++) {
            float* c = acc[mf][nf];
            int n  = bn + wn * 32 + nf * 8 + gc;
            int m0 = bm + wm * 64 + mf * 16 + gr;
#pragma unroll
            for (int half = 0; half < 2; half++) {
                int m = m0 + half * 8;
                float v0 = c[half * 2]     + bias[n];
                float v1 = c[half * 2 + 1] + bias[n + 1];
                if (EPI == 0) {
                    *(float2*)((float*)Cout + (size_t)m * N + n) = make_float2(v0, v1);
                } else if (EPI == 2) {
                    float x = v0;
                    float gx = 0.5f * x * (1.0f + tanhf(0.7978845608028654f * (x + 0.044715f * x * x * x)));
                    x = v1;
                    float gy = 0.5f * x * (1.0f + tanhf(0.7978845608028654f * (x + 0.044715f * x * x * x)));
                    *(__nv_bfloat162*)((__nv_bfloat16*)Cout + (size_t)m * N + n) =
                        __floats2bfloat162_rn(gx, gy);
                } else if (EPI == 3) {
                    int b = m >> 9;
                    const float* ep = E + (size_t)b * 3 * ND + 2 * ND + n;
                    const float* zp = Z + (size_t)m * N + n;
                    *(float2*)((float*)Cout + (size_t)m * N + n) =
                        make_float2(zp[0] + v0 * ep[0], zp[1] + v1 * ep[1]);
                } else if (EPI == 4) {
                    *(__nv_bfloat162*)((__nv_bfloat16*)Cout + (size_t)m * N + n) =
                        __floats2bfloat162_rn(v0, v1);
                } else { // EPI == 6: fp16 head-major
                    int b = m >> 10, t = m & (S2 - 1), h = n >> 6;
                    __half* dst = (__half*)Cout + ((size_t)(b * NH + h) * S2 + t) * NHD + (n & 63);
                    *(__half2*)dst = __floats2half2_rn(v0, v1);
                }
            }
        }
    }
}

// ---------------------------------------------------------------------------
// Flash attention via fp16 mma.sync. One block per (b, h, 128 q-rows).
// 8 warps x 16 q-rows. BK=64 double-buffered cp.async.
// ---------------------------------------------------------------------------
#define AT_PITCH   144
#define AT_QBYTES  (128 * AT_PITCH)
#define AT_KVBYTES (64 * AT_PITCH)
#define AT_SMEM    (AT_QBYTES + 4 * AT_KVBYTES)

__global__ void __launch_bounds__(256) attn_mma_kernel()
{
    extern __shared__ char sm_[];
    uint32_t Qb = smem_u32(sm_);
    uint32_t Kb = Qb + AT_QBYTES;
    uint32_t Vb = Kb + 2 * AT_KVBYTES;

    int b = blockIdx.z, h = blockIdx.y, qt = blockIdx.x;
    int tid = threadIdx.x, lane = tid & 31, wid = tid >> 5;

    const __half* qg = g_qhh + ((size_t)(b * NH + h) * S2 + qt * 128) * NHD;
    const __half* kg = g_khh + (size_t)(b * NH + h) * S2 * NHD;
    const __half* vg = g_vhh + (size_t)(b * NH + h) * S2 * NHD;

    // Q tile (16KB)
    for (int i = tid; i < 1024; i += 256) {
        int row = i >> 3, c = i & 7;
        cp16(Qb + row * AT_PITCH + c * 16, qg + row * 64 + c * 8);
    }
    asm volatile("cp.async.commit_group;" ::: "memory");

    // KV chunk 0
    for (int i = tid; i < 512; i += 256) {
        int row = i >> 3, c = i & 7;
        cp16(Kb + row * AT_PITCH + c * 16, kg + row * 64 + c * 8);
        cp16(Vb + row * AT_PITCH + c * 16, vg + row * 64 + c * 8);
    }
    asm volatile("cp.async.commit_group;" ::: "memory");

    uint32_t q_off    = Qb + (wid * 16 + (lane & 15)) * AT_PITCH + (lane >> 4) * 16;
    uint32_t k_rowpat = (lane >> 4) * 8 + (lane & 7);
    uint32_t k_colpat = ((lane >> 3) & 1) * 16;
    uint32_t v_rowpat = lane & 15;
    uint32_t v_colpat = ((lane >> 4) & 1) * 16;

    float o[8][4] = {};
    float mrow0 = -1e30f, mrow1 = -1e30f;
    float lrow0 = 0.f, lrow1 = 0.f;

    for (int kt = 0; kt < 16; kt++) {
        if (kt + 1 < 16) {
            uint32_t kd = Kb + ((kt + 1) & 1) * AT_KVBYTES;
            uint32_t vd = Vb + ((kt + 1) & 1) * AT_KVBYTES;
            const __half* ks = kg + (size_t)(kt + 1) * 64 * 64;
            const __half* vs = vg + (size_t)(kt + 1) * 64 * 64;
            for (int i = tid; i < 512; i += 256) {
                int row = i >> 3, c = i & 7;
                cp16(kd + row * AT_PITCH + c * 16, ks + row * 64 + c * 8);
                cp16(vd + row * AT_PITCH + c * 16, vs + row * 64 + c * 8);
            }
        }
        asm volatile("cp.async.commit_group;" ::: "memory");
        asm volatile("cp.async.wait_group 1;" ::: "memory");
        __syncthreads();

        uint32_t ksm = Kb + (kt & 1) * AT_KVBYTES;
        uint32_t vsm = Vb + (kt & 1) * AT_KVBYTES;

        // S = Q K^T  (16 x 64 per warp)
        float s[8][4] = {};
#pragma unroll
        for (int kk = 0; kk < 4; kk++) {
            uint32_t qf[4];
            ldm4(q_off + kk * 32, qf);
#pragma unroll
            for (int nt = 0; nt < 4; nt++) {
                uint32_t kf[4];
                ldm4(ksm + (nt * 16 + k_rowpat) * AT_PITCH + k_colpat + kk * 32, kf);
                mma16816h(s[nt * 2],     qf, kf);
                mma16816h(s[nt * 2 + 1], qf, kf + 2);
            }
        }

        // online softmax (rows gr, gr+8; quad shfl reduce)
        float mn0 = mrow0, mn1 = mrow1;
#pragma unroll
        for (int j = 0; j < 8; j++) {
            s[j][0] *= 0.125f; s[j][1] *= 0.125f; s[j][2] *= 0.125f; s[j][3] *= 0.125f;
            mn0 = fmaxf(mn0, fmaxf(s[j][0], s[j][1]));
            mn1 = fmaxf(mn1, fmaxf(s[j][2], s[j][3]));
        }
        mn0 = fmaxf(mn0, __shfl_xor_sync(0xffffffffu, mn0, 1));
        mn0 = fmaxf(mn0, __shfl_xor_sync(0xffffffffu, mn0, 2));
        mn1 = fmaxf(mn1, __shfl_xor_sync(0xffffffffu, mn1, 1));
        mn1 = fmaxf(mn1, __shfl_xor_sync(0xffffffffu, mn1, 2));
        float al0 = __expf(mrow0 - mn0), al1 = __expf(mrow1 - mn1);
        mrow0 = mn0; mrow1 = mn1;

        float ls0 = 0.f, ls1 = 0.f;
        uint32_t p[8][2];
#pragma unroll
        for (int j = 0; j < 8; j++) {
            float p0 = __expf(s[j][0] - mn0), p1 = __expf(s[j][1] - mn0);
            float p2 = __expf(s[j][2] - mn1), p3 = __expf(s[j][3] - mn1);
            ls0 += p0 + p1; ls1 += p2 + p3;
            p[j][0] = h2pack(p0, p1);
            p[j][1] = h2pack(p2, p3);
        }
        lrow0 = lrow0 * al0 + ls0;
        lrow1 = lrow1 * al1 + ls1;
#pragma unroll
        for (int j = 0; j < 8; j++) {
            o[j][0] *= al0; o[j][1] *= al0; o[j][2] *= al1; o[j][3] *= al1;
        }

        // O += P V
#pragma unroll
        for (int kp = 0; kp < 4; kp++) {
            uint32_t af[4] = { p[2 * kp][0], p[2 * kp][1], p[2 * kp + 1][0], p[2 * kp + 1][1] };
#pragma unroll
            for (int nt = 0; nt < 4; nt++) {
                uint32_t vf[4];
                ldm4t(vsm + (kp * 16 + v_rowpat) * AT_PITCH + nt * 32 + v_colpat, vf);
                mma16816h(o[nt * 2],     af, vf);
                mma16816h(o[nt * 2 + 1], af, vf + 2);
            }
        }
        __syncthreads();
    }

    float lt0 = lrow0;
    lt0 += __shfl_xor_sync(0xffffffffu, lt0, 1);
    lt0 += __shfl_xor_sync(0xffffffffu, lt0, 2);
    float lt1 = lrow1;
    lt1 += __shfl_xor_sync(0xffffffffu, lt1, 1);
    lt1 += __shfl_xor_sync(0xffffffffu, lt1, 2);
    float inv0 = 1.0f / lt0, inv1 = 1.0f / lt1;

    int gr = lane >> 2, qc = (lane & 3) * 2;
    int r0 = qt * 128 + wid * 16 + gr;
    size_t base0 = ((size_t)b * S2 + r0) * ND + h * 64 + qc;
    size_t base1 = base0 + (size_t)8 * ND;
#pragma unroll
    for (int j = 0; j < 8; j++) {
        *(__nv_bfloat162*)&g_ob[base0 + j * 8] =
            __floats2bfloat162_rn(o[j][0] * inv0, o[j][1] * inv0);
        *(__nv_bfloat162*)&g_ob[base1 + j * 8] =
            __floats2bfloat162_rn(o[j][2] * inv1, o[j][3] * inv1);
    }
}

// ---------------------------------------------------------------------------
// Launch sequence
// ---------------------------------------------------------------------------
extern "C" void kernel_launch(void* const* d_in, const int* in_sizes, int n_in,
                              void* d_out, int out_size)
{
    const float* state_z    = (const float*)d_in[0];
    const float* action_z   = (const float*)d_in[1];
    const float* e          = (const float*)d_in[2];
    const float* qkv_s_w    = (const float*)d_in[3];
    const float* qkv_s_b    = (const float*)d_in[4];
    const float* qkv_a_w    = (const float*)d_in[5];
    const float* qkv_a_b    = (const float*)d_in[6];
    const float* attn_in_w  = (const float*)d_in[7];
    const float* attn_in_b  = (const float*)d_in[8];
    const float* attn_out_w = (const float*)d_in[9];
    const float* attn_out_b = (const float*)d_in[10];
    const float* mw1s       = (const float*)d_in[11];
    const float* mb1s       = (const float*)d_in[12];
    const float* mw2s       = (const float*)d_in[13];
    const float* mb2s       = (const float*)d_in[14];
    const float* mw1a       = (const float*)d_in[15];
    const float* mb1a       = (const float*)d_in[16];
    const float* mw2a       = (const float*)d_in[17];
    const float* mb2a       = (const float*)d_in[18];
    float* out = (float*)d_out;

    float *qkvs, *qkva;
    __half *qhh, *khh, *vhh;
    __nv_bfloat16 *xsb, *xab, *qb, *kb, *vb, *ob, *yb, *h1b;
    __nv_bfloat16 *wqs, *wqa, *wai, *wao, *w1s, *w2s, *w1a, *w2a;
    cudaGetSymbolAddress((void**)&qkvs, g_qkvs);
    cudaGetSymbolAddress((void**)&qkva, g_qkva);
    cudaGetSymbolAddress((void**)&qhh,  g_qhh);
    cudaGetSymbolAddress((void**)&khh,  g_khh);
    cudaGetSymbolAddress((void**)&vhh,  g_vhh);
    cudaGetSymbolAddress((void**)&xsb,  g_xsb);
    cudaGetSymbolAddress((void**)&xab,  g_xab);
    cudaGetSymbolAddress((void**)&qb,   g_qb);
    cudaGetSymbolAddress((void**)&kb,   g_kb);
    cudaGetSymbolAddress((void**)&vb,   g_vb);
    cudaGetSymbolAddress((void**)&ob,   g_ob);
    cudaGetSymbolAddress((void**)&yb,   g_yb);
    cudaGetSymbolAddress((void**)&h1b,  g_h1b);
    cudaGetSymbolAddress((void**)&wqs,  g_wqs);
    cudaGetSymbolAddress((void**)&wqa,  g_wqa);
    cudaGetSymbolAddress((void**)&wai,  g_wai);
    cudaGetSymbolAddress((void**)&wao,  g_wao);
    cudaGetSymbolAddress((void**)&w1s,  g_w1s);
    cudaGetSymbolAddress((void**)&w2s,  g_w2s);
    cudaGetSymbolAddress((void**)&w1a,  g_w1a);
    cudaGetSymbolAddress((void**)&w2a,  g_w2a);

    cudaFuncSetAttribute(gemm_mma<0>, cudaFuncAttributeMaxDynamicSharedMemorySize, DSMEM_BYTES);
    cudaFuncSetAttribute(gemm_mma<2>, cudaFuncAttributeMaxDynamicSharedMemorySize, DSMEM_BYTES);
    cudaFuncSetAttribute(gemm_mma<3>, cudaFuncAttributeMaxDynamicSharedMemorySize, DSMEM_BYTES);
    cudaFuncSetAttribute(gemm_mma<4>, cudaFuncAttributeMaxDynamicSharedMemorySize, DSMEM_BYTES);
    cudaFuncSetAttribute(gemm_mma<6>, cudaFuncAttributeMaxDynamicSharedMemorySize, DSMEM_BYTES);
    cudaFuncSetAttribute(attn_mma_kernel, cudaFuncAttributeMaxDynamicSharedMemorySize, AT_SMEM);

    // weight conversion fp32 -> bf16
    {
        struct { const float* s; __nv_bfloat16* d; int n; } cv[8] = {
            {qkv_s_w, wqs, D3 * ND}, {qkv_a_w, wqa, D3 * ND},
            {attn_in_w, wai, D3 * ND}, {attn_out_w, wao, ND * ND},
            {mw1s, w1s, D4 * ND}, {mw2s, w2s, ND * D4},
            {mw1a, w1a, D4 * ND}, {mw2a, w2a, ND * D4},
        };
        for (int i = 0; i < 8; i++)
            f2bf_kernel<<<(cv[i].n / 4 + 255) / 256, 256>>>(cv[i].s, cv[i].d, cv[i].n);
    }

    // modulation -> bf16 activations
    modulate_kernel<<<(BSq * ND) / 256, 256>>>(state_z, action_z, e);

    // QKV GEMMs
    dim3 g1(D3 / 128, BSq / 128);
    gemm_mma<0><<<g1, 256, DSMEM_BYTES>>>(xsb, wqs, qkv_s_b, qkvs, BSq, D3, ND, nullptr, nullptr, 0, 0);
    gemm_mma<0><<<g1, 256, DSMEM_BYTES>>>(xab, wqa, qkv_a_b, qkva, BSq, D3, ND, nullptr, nullptr, 0, 0);

    // RoPE + concat (bf16 out)
    rope_kernel<<<(NB * S2 * (ND / 2)) / 256, 256>>>();

    // head projections -> fp16 head-major
    dim3 g2(ND / 128, BT / 128);
    gemm_mma<6><<<g2, 256, DSMEM_BYTES>>>(qb, wai,               attn_in_b,          qhh, BT, ND, ND, nullptr, nullptr, 0, 0);
    gemm_mma<6><<<g2, 256, DSMEM_BYTES>>>(kb, wai + ND * ND,     attn_in_b + ND,     khh, BT, ND, ND, nullptr, nullptr, 0, 0);
    gemm_mma<6><<<g2, 256, DSMEM_BYTES>>>(vb, wai + 2 * ND * ND, attn_in_b + 2 * ND, vhh, BT, ND, ND, nullptr, nullptr, 0, 0);

    // attention (fp16 mma)
    dim3 ga(S2 / 128, NH, NB);
    attn_mma_kernel<<<ga, 256, AT_SMEM>>>();

    // output projection -> bf16
    gemm_mma<4><<<g2, 256, DSMEM_BYTES>>>(ob, wao, attn_out_b, yb, BT, ND, ND, nullptr, nullptr, 0, 0);

    // MLPs with gated residual
    dim3 g3(D4 / 128, BSq / 128);
    dim3 g4(ND / 128, BSq / 128);
    gemm_mma<2><<<g3, 256, DSMEM_BYTES>>>(yb,  w1s, mb1s, h1b,            BSq, D4, ND, nullptr,  nullptr, 1, 0);
    gemm_mma<3><<<g4, 256, DSMEM_BYTES>>>(h1b, w2s, mb2s, out,            BSq, ND, D4, state_z,  e,       0, 0);
    gemm_mma<2><<<g3, 256, DSMEM_BYTES>>>(yb,  w1a, mb1a, h1b,            BSq, D4, ND, nullptr,  nullptr, 1, 1);
    gemm_mma<3><<<g4, 256, DSMEM_BYTES>>>(h1b, w2a, mb2a, out + (size_t)BSq * ND, BSq, ND, D4, action_z, e, 0, 0);
}